// round 9
// baseline (speedup 1.0000x reference)
#include <cuda_runtime.h>
#include <math.h>
#include <stdint.h>

#define B 32
#define DIN 2048
#define D 128
#define NREPS 400000
#define ADIM 7
#define KSEL 5

#define GRID_MAIN 148
#define TILE_N 128
#define NTILES (NREPS / TILE_N)   /* 3125, exact */
#define ENC_CHUNKS 16

/* smem layout (bytes) */
#define ABUF(buf)  ((buf) * 98304)             /* A frag planes: [w8=w*8+kk][p][lane*16 + reg*4] */
#define BT_OFF     196608                       /* B frag table: [(p*8+kk)*4+nb][lane*8], 24576 B */
#define NORM_OFF   221184                       /* 2 bufs x 128 floats */
#define SMEM_TOTAL 222208

/* ---------------- device scratch ---------------- */
__device__ float g_enc_part[ENC_CHUNKS][B][D];
__device__ float g_batch[B * D];
__device__ float g_anorm[B];
__device__ float g_ckey[B * GRID_MAIN * KSEL];
__device__ int   g_cidx[B * GRID_MAIN * KSEL];

/* ---------------- helpers ---------------- */
__device__ __forceinline__ void split3(float v, unsigned& h0, unsigned& h1, unsigned& h2) {
    unsigned u = __float_as_uint(v);
    h0 = u & 0xFFFF0000u;
    float v1 = v - __uint_as_float(h0);
    unsigned u1 = __float_as_uint(v1);
    h1 = u1 & 0xFFFF0000u;
    float v2 = v1 - __uint_as_float(h1);
    h2 = __float_as_uint(v2) & 0xFFFF0000u;
}
/* pack bf16x2: low = even element, high = odd element (consistent on A and B) */
__device__ __forceinline__ unsigned packbf(unsigned he, unsigned ho) {
    return __byte_perm(he, ho, 0x7632);
}
__device__ __forceinline__ void mma16816(float* c, uint4 a, uint2 b) {
    asm volatile(
        "mma.sync.aligned.m16n8k16.row.col.f32.bf16.bf16.f32 "
        "{%0,%1,%2,%3}, {%4,%5,%6,%7}, {%8,%9}, {%0,%1,%2,%3};"
        : "+f"(c[0]), "+f"(c[1]), "+f"(c[2]), "+f"(c[3])
        : "r"(a.x), "r"(a.y), "r"(a.z), "r"(a.w), "r"(b.x), "r"(b.y));
}

/* ================= encoder split-K partial ================= */
__global__ void enc_partial(const float* __restrict__ x,
                            const float* __restrict__ W) {
    __shared__ float xs[128];
    int b = blockIdx.x, c = blockIdx.y, t = threadIdx.x;
    xs[t] = x[b * DIN + c * 128 + t];
    __syncthreads();
    const float* Wp = W + (c * 128) * D + t;
    float a0 = 0.f, a1 = 0.f, a2 = 0.f, a3 = 0.f;
#pragma unroll
    for (int k = 0; k < 128; k += 4) {
        a0 = fmaf(xs[k + 0], Wp[(k + 0) * D], a0);
        a1 = fmaf(xs[k + 1], Wp[(k + 1) * D], a1);
        a2 = fmaf(xs[k + 2], Wp[(k + 2) * D], a2);
        a3 = fmaf(xs[k + 3], Wp[(k + 3) * D], a3);
    }
    g_enc_part[c][b][t] = (a0 + a1) + (a2 + a3);
}

/* ================= encoder reduce + norms ================= */
__global__ void enc_reduce(const float* __restrict__ bias) {
    __shared__ float red[4];
    int b = blockIdx.x, t = threadIdx.x;
    float s = bias[t];
#pragma unroll
    for (int c = 0; c < ENC_CHUNKS; c++) s += g_enc_part[c][b][t];
    g_batch[b * D + t] = s;
    float sq = s * s;
#pragma unroll
    for (int o = 16; o > 0; o >>= 1) sq += __shfl_down_sync(0xffffffffu, sq, o);
    if ((t & 31) == 0) red[t >> 5] = sq;
    __syncthreads();
    if (t == 0) g_anorm[b] = red[0] + red[1] + red[2] + red[3];
}

/* ---- convert one tile (128 rows) into A fragment planes + row norms ----
   thread t: row r = t>>1, half h = t&1 (dims 64h..64h+63).
   Fragment layout (mma.sync m16n8k16 A, row-major):
     warp-slab w = r>>4, gr = r&15; word (dims 16kk+2widx, +1):
     lane = (gr&7)*4 + (widx&3), reg = (gr>>3) + ((widx>>2)<<1).           */
__device__ __forceinline__ void convert_tile(const float* __restrict__ reps, int rowbase,
                                             char* smem, int buf, int t, float* normsh) {
    int r = t >> 1, h = t & 1;
    int wslab = r >> 4, gr = r & 15;
    const float4* src4 = (const float4*)(reps + (size_t)(rowbase + r) * D + h * 64);
    unsigned regsel = (unsigned)(gr >> 3);      /* +0 or +1 */
    unsigned lanebase = (unsigned)((gr & 7) * 4);
    float nacc = 0.f;
#pragma unroll
    for (int j2 = 0; j2 < 4; j2++) {
        int kk = h * 4 + j2;
        float4 f0 = src4[j2 * 4 + 0];
        float4 f1 = src4[j2 * 4 + 1];
        float4 f2 = src4[j2 * 4 + 2];
        float4 f3 = src4[j2 * 4 + 3];
        const float v[16] = {f0.x, f0.y, f0.z, f0.w, f1.x, f1.y, f1.z, f1.w,
                             f2.x, f2.y, f2.z, f2.w, f3.x, f3.y, f3.z, f3.w};
        unsigned base0 = (unsigned)ABUF(buf) + (unsigned)(((wslab * 8 + kk) * 3) * 512);
#pragma unroll
        for (int widx = 0; widx < 8; widx++) {
            float va = v[2 * widx], vb = v[2 * widx + 1];
            unsigned a0, a1, a2, b0, b1, b2;
            split3(va, a0, a1, a2);
            split3(vb, b0, b1, b2);
            nacc = fmaf(va, va, fmaf(vb, vb, nacc));
            unsigned reg = regsel + ((unsigned)(widx >> 2) << 1);
            unsigned off = base0 + (lanebase + (unsigned)(widx & 3)) * 16u + reg * 4u;
            *(unsigned*)(smem + off)         = packbf(a0, b0);
            *(unsigned*)(smem + off + 512u)  = packbf(a1, b1);
            *(unsigned*)(smem + off + 1024u) = packbf(a2, b2);
        }
    }
    nacc += __shfl_xor_sync(0xffffffffu, nacc, 1);
    if (h == 0) normsh[buf * 128 + r] = nacc;
}

/* ================= main distance kernel: split-bf16 mma.sync ================= */
__global__ void __launch_bounds__(256, 1) dist_kernel(const float* __restrict__ reps) {
    extern __shared__ char smem[];
    float* normsh = (float*)(smem + NORM_OFF);

    int t = threadIdx.x, wid = t >> 5, lane = t & 31;
    int g = lane >> 2, qt = lane & 3;
    int bid = blockIdx.x;

    /* ---- build B fragment table (batch, 3 planes) once ----
       B frag (col-major 16x8): lane g=n, qt over k: b0={B[16kk+2qt][n],B[..+1][n]},
       b1={B[16kk+2qt+8][n],B[..+9][n]}.  entry addr: ((p*8+kk)*4+nb)*256 + lane*8 */
    for (int e = t; e < 3072; e += 256) {
        int le = e & 31, nb = (e >> 5) & 3, kk = (e >> 7) & 7, p = e >> 10;
        int ge = le >> 2, te = le & 3;
        int bcol = 8 * nb + ge;
        int k0 = 16 * kk + 2 * te;
        unsigned h[4][3];
#pragma unroll
        for (int q = 0; q < 4; q++) {
            int k = k0 + (q >> 1) * 8 + (q & 1);
            split3(g_batch[bcol * D + k], h[q][0], h[q][1], h[q][2]);
        }
        uint2 w2;
        w2.x = packbf(h[0][p], h[1][p]);
        w2.y = packbf(h[2][p], h[3][p]);
        *(uint2*)(smem + BT_OFF + ((size_t)((p * 8 + kk) * 4 + nb)) * 256 + le * 8) = w2;
    }

    /* ---- convert tile 0 ---- */
    convert_tile(reps, bid * TILE_N, smem, 0, t, normsh);
    __syncthreads();

    /* 8 per-batch top-5 lists: list li covers batch 8*(li>>1) + 2*qt + (li&1) */
    float tk[8][5]; int tn[8][5];
#pragma unroll
    for (int li = 0; li < 8; li++)
#pragma unroll
        for (int j = 0; j < 5; j++) { tk[li][j] = 3.0e38f; tn[li][j] = 0; }

    int cur = 0;
    for (int tile = bid; tile < NTILES; tile += GRID_MAIN) {
        int tb = tile * TILE_N;

        /* ---- compute: warp slab = wid (rows 16*wid..+15), all 32 batches ---- */
        float acc[4][4];
#pragma unroll
        for (int nb = 0; nb < 4; nb++)
#pragma unroll
            for (int q = 0; q < 4; q++) acc[nb][q] = 0.f;

        const char* abase = smem + ABUF(cur) + (size_t)(wid * 8) * 3 * 512 + lane * 16;
        const char* btab = smem + BT_OFF + lane * 8;
#pragma unroll 2
        for (int kk = 0; kk < 8; kk++) {
            uint4 A0 = *(const uint4*)(abase + (kk * 3 + 0) * 512);
            uint4 A1 = *(const uint4*)(abase + (kk * 3 + 1) * 512);
            uint4 A2 = *(const uint4*)(abase + (kk * 3 + 2) * 512);
#pragma unroll
            for (int nb = 0; nb < 4; nb++) {
                uint2 B0 = *(const uint2*)(btab + (size_t)((0 * 8 + kk) * 4 + nb) * 256);
                uint2 B1 = *(const uint2*)(btab + (size_t)((1 * 8 + kk) * 4 + nb) * 256);
                uint2 B2 = *(const uint2*)(btab + (size_t)((2 * 8 + kk) * 4 + nb) * 256);
                mma16816(acc[nb], A0, B0);
                mma16816(acc[nb], A0, B1);
                mma16816(acc[nb], A1, B0);
                mma16816(acc[nb], A1, B1);
                mma16816(acc[nb], A0, B2);
                mma16816(acc[nb], A2, B0);
            }
        }

        /* ---- keys + insert: c0=(row g, b 2qt), c1=(g, +1), c2=(g+8, 2qt), c3=(g+8, +1) ---- */
        float nn0 = normsh[cur * 128 + wid * 16 + g];
        float nn1 = normsh[cur * 128 + wid * 16 + g + 8];
        int r0 = tb + wid * 16 + g;
#pragma unroll
        for (int nb = 0; nb < 4; nb++) {
#pragma unroll
            for (int s = 0; s < 2; s++) {
                int li = nb * 2 + s;
                float k0v = nn0 - 2.0f * acc[nb][s];        /* row r0   */
                float k1v = nn1 - 2.0f * acc[nb][2 + s];    /* row r0+8 */
#pragma unroll
                for (int which = 0; which < 2; which++) {
                    float kv = which ? k1v : k0v;
                    int   iv = which ? (r0 + 8) : r0;
                    if (kv < tk[li][4]) {
                        tk[li][4] = kv; tn[li][4] = iv;
#pragma unroll
                        for (int m = 4; m > 0; m--) {
                            if (tk[li][m] < tk[li][m - 1]) {
                                float fk = tk[li][m]; tk[li][m] = tk[li][m - 1]; tk[li][m - 1] = fk;
                                int ii = tn[li][m]; tn[li][m] = tn[li][m - 1]; tn[li][m - 1] = ii;
                            }
                        }
                    }
                }
            }
        }

        /* ---- convert next tile into other buffer ---- */
        int next = tile + GRID_MAIN;
        if (next < NTILES)
            convert_tile(reps, next * TILE_N, smem, cur ^ 1, t, normsh);
        __syncthreads();
        cur ^= 1;
    }

    /* ---- merge: dump all lists, then thread b<32 scans its 64 lists ---- */
    float* mk = (float*)smem;              /* [256][8][5] keys, 40960 B */
    int*   mi = (int*)(smem + 49152);      /* [256][8][5] idx */
#pragma unroll
    for (int li = 0; li < 8; li++)
#pragma unroll
        for (int j = 0; j < 5; j++) {
            mk[(t * 8 + li) * 5 + j] = tk[li][j];
            mi[(t * 8 + li) * 5 + j] = tn[li][j];
        }
    __syncthreads();

    if (t < 32) {
        int b = t;
        int li = (b >> 3) * 2 + (b & 1);
        int qb = (b >> 1) & 3;
        float fk[5]; int fn[5];
#pragma unroll
        for (int j = 0; j < 5; j++) { fk[j] = 3.0e38f; fn[j] = 0; }
        for (int m = 0; m < 64; m++) {
            int tt = qb + 4 * m;
            int base = (tt * 8 + li) * 5;
#pragma unroll
            for (int j = 0; j < 5; j++) {
                float kv = mk[base + j];
                if (kv < fk[4]) {
                    int iv = mi[base + j];
                    fk[4] = kv; fn[4] = iv;
#pragma unroll
                    for (int m2 = 4; m2 > 0; m2--) {
                        if (fk[m2] < fk[m2 - 1]) {
                            float a2 = fk[m2]; fk[m2] = fk[m2 - 1]; fk[m2 - 1] = a2;
                            int i2 = fn[m2]; fn[m2] = fn[m2 - 1]; fn[m2 - 1] = i2;
                        }
                    }
                } else break;  /* lists are sorted */
            }
        }
        int basec = (b * GRID_MAIN + bid) * KSEL;
#pragma unroll
        for (int j = 0; j < 5; j++) { g_ckey[basec + j] = fk[j]; g_cidx[basec + j] = fn[j]; }
    }
}

/* ================= final: merge 740 candidates/batch, softmax, gather ================= */
__global__ void __launch_bounds__(256) final_kernel(const float* __restrict__ actions,
                                                    float* __restrict__ out) {
    __shared__ float skey[8 * KSEL];
    __shared__ int   sidx[8 * KSEL];
    int b = blockIdx.x, t = threadIdx.x;
    int w = t >> 5, lane = t & 31;

    float tk[5]; int tn[5];
#pragma unroll
    for (int j = 0; j < 5; j++) { tk[j] = 3.0e38f; tn[j] = 0; }

    const int total = GRID_MAIN * KSEL;
    const float* ck = g_ckey + b * total;
    const int*   ci = g_cidx + b * total;
    for (int i = t; i < total; i += 256) {
        float key = ck[i];
        if (key < tk[4]) {
            int idx = ci[i];
            tk[4] = key; tn[4] = idx;
#pragma unroll
            for (int j = 4; j > 0; j--) {
                if (tk[j] < tk[j - 1]) {
                    float fk = tk[j]; tk[j] = tk[j - 1]; tk[j - 1] = fk;
                    int ii = tn[j]; tn[j] = tn[j - 1]; tn[j - 1] = ii;
                }
            }
        }
    }
#pragma unroll
    for (int o = 16; o > 0; o >>= 1) {
        float ok[5]; int on[5];
#pragma unroll
        for (int j = 0; j < 5; j++) {
            ok[j] = __shfl_xor_sync(0xffffffffu, tk[j], o);
            on[j] = __shfl_xor_sync(0xffffffffu, tn[j], o);
        }
#pragma unroll
        for (int j = 0; j < 5; j++) {
            float key = ok[j]; int idx = on[j];
            if (key < tk[4]) {
                tk[4] = key; tn[4] = idx;
#pragma unroll
                for (int m = 4; m > 0; m--) {
                    if (tk[m] < tk[m - 1]) {
                        float fk = tk[m]; tk[m] = tk[m - 1]; tk[m - 1] = fk;
                        int ii = tn[m]; tn[m] = tn[m - 1]; tn[m - 1] = ii;
                    }
                }
            }
        }
    }
    if (lane == 0) {
#pragma unroll
        for (int j = 0; j < 5; j++) { skey[w * KSEL + j] = tk[j]; sidx[w * KSEL + j] = tn[j]; }
    }
    __syncthreads();

    if (t == 0) {
        float fk[5]; int fn[5];
#pragma unroll
        for (int j = 0; j < 5; j++) { fk[j] = skey[j]; fn[j] = sidx[j]; }
        for (int i = KSEL; i < 8 * KSEL; i++) {
            float key = skey[i];
            if (key < fk[4]) {
                int idx = sidx[i];
                fk[4] = key; fn[4] = idx;
#pragma unroll
                for (int m = 4; m > 0; m--) {
                    if (fk[m] < fk[m - 1]) {
                        float a2 = fk[m]; fk[m] = fk[m - 1]; fk[m - 1] = a2;
                        int i2 = fn[m]; fn[m] = fn[m - 1]; fn[m - 1] = i2;
                    }
                }
            }
        }
        float an = g_anorm[b];
        float dloc[KSEL];
        float dmin = 3.0e38f;
#pragma unroll
        for (int j = 0; j < KSEL; j++) {
            dloc[j] = sqrtf(fmaxf(an + fk[j], 1e-12f));
            dmin = fminf(dmin, dloc[j]);
        }
        float wsum = 0.f;
        float pred[ADIM];
#pragma unroll
        for (int a = 0; a < ADIM; a++) pred[a] = 0.f;
#pragma unroll
        for (int j = 0; j < KSEL; j++) {
            float wgt = expf(-(dloc[j] - dmin));
            wsum += wgt;
            const float* arow = actions + (size_t)fn[j] * ADIM;
#pragma unroll
            for (int a = 0; a < ADIM; a++) pred[a] = fmaf(wgt, arow[a], pred[a]);
        }
        float inv = 1.0f / wsum;
#pragma unroll
        for (int a = 0; a < ADIM; a++) out[b * ADIM + a] = pred[a] * inv;
    }
}

/* ================= launch ================= */
extern "C" void kernel_launch(void* const* d_in, const int* in_sizes, int n_in,
                              void* d_out, int out_size) {
    (void)in_sizes; (void)n_in; (void)out_size;
    const float* x       = (const float*)d_in[0];
    const float* W       = (const float*)d_in[1];
    const float* bias    = (const float*)d_in[2];
    const float* reps    = (const float*)d_in[3];
    const float* actions = (const float*)d_in[4];
    float* out = (float*)d_out;

    cudaFuncSetAttribute(dist_kernel, cudaFuncAttributeMaxDynamicSharedMemorySize, SMEM_TOTAL);

    enc_partial<<<dim3(B, ENC_CHUNKS), 128>>>(x, W);
    enc_reduce<<<B, 128>>>(bias);
    dist_kernel<<<GRID_MAIN, 256, SMEM_TOTAL>>>(reps);
    final_kernel<<<B, 256>>>(actions, out);
}

// round 11
// speedup vs baseline: 1.5757x; 1.5757x over previous
#include <cuda_runtime.h>
#include <math.h>
#include <stdint.h>

#define B 32
#define DIN 2048
#define D 128
#define NREPS 400000
#define ADIM 7
#define KSEL 5

#define GRID_MAIN 148
#define TILE_N 128
#define NTILES (NREPS / TILE_N)   /* 3125, exact */
#define ENC_CHUNKS 16

/* smem layout (bytes) */
#define ABUF(buf)   ((buf) * 65536)   /* 2 planes x 32KB: row-major bf16, 256B/row, XOR-swizzled */
#define APLANE      32768
#define BT_OFF      131072            /* B frag table: [(p*8+kk)*4+nb][lane*8], 16384 B */
#define NPART_OFF   147456            /* [buf][h][r] floats: 4*128*4 = 2048 B */
#define SMEM_TOTAL  150528

/* ---------------- device scratch ---------------- */
__device__ float g_enc_part[ENC_CHUNKS][B][D];
__device__ float g_batch[B * D];
__device__ float g_anorm[B];
__device__ float g_ckey[B * GRID_MAIN * KSEL];
__device__ int   g_cidx[B * GRID_MAIN * KSEL];

/* ---------------- helpers ---------------- */
__device__ __forceinline__ void split2(float v, unsigned& h0, unsigned& h1) {
    unsigned u = __float_as_uint(v);
    h0 = u & 0xFFFF0000u;
    float v1 = v - __uint_as_float(h0);
    h1 = __float_as_uint(v1) & 0xFFFF0000u;
}
__device__ __forceinline__ void split3(float v, unsigned& h0, unsigned& h1, unsigned& h2) {
    unsigned u = __float_as_uint(v);
    h0 = u & 0xFFFF0000u;
    float v1 = v - __uint_as_float(h0);
    unsigned u1 = __float_as_uint(v1);
    h1 = u1 & 0xFFFF0000u;
    float v2 = v1 - __uint_as_float(h1);
    h2 = __float_as_uint(v2) & 0xFFFF0000u;
}
__device__ __forceinline__ unsigned packbf(unsigned he, unsigned ho) {
    return __byte_perm(he, ho, 0x7632);
}
__device__ __forceinline__ void mma16816(float* c, uint4 a, uint2 b) {
    asm volatile(
        "mma.sync.aligned.m16n8k16.row.col.f32.bf16.bf16.f32 "
        "{%0,%1,%2,%3}, {%4,%5,%6,%7}, {%8,%9}, {%0,%1,%2,%3};"
        : "+f"(c[0]), "+f"(c[1]), "+f"(c[2]), "+f"(c[3])
        : "r"(a.x), "r"(a.y), "r"(a.z), "r"(a.w), "r"(b.x), "r"(b.y));
}
__device__ __forceinline__ uint4 ldsm_x4(unsigned addr) {
    uint4 r;
    asm volatile("ldmatrix.sync.aligned.m8n8.x4.shared.b16 {%0,%1,%2,%3}, [%4];"
                 : "=r"(r.x), "=r"(r.y), "=r"(r.z), "=r"(r.w) : "r"(addr));
    return r;
}
__device__ __forceinline__ unsigned smem_u32(const void* p) {
    unsigned a;
    asm("{ .reg .u64 t; cvta.to.shared.u64 t, %1; cvt.u32.u64 %0, t; }" : "=r"(a) : "l"(p));
    return a;
}

/* ================= encoder split-K partial ================= */
__global__ void enc_partial(const float* __restrict__ x,
                            const float* __restrict__ W) {
    __shared__ float xs[128];
    int b = blockIdx.x, c = blockIdx.y, t = threadIdx.x;
    xs[t] = x[b * DIN + c * 128 + t];
    __syncthreads();
    const float* Wp = W + (c * 128) * D + t;
    float a0 = 0.f, a1 = 0.f, a2 = 0.f, a3 = 0.f;
#pragma unroll
    for (int k = 0; k < 128; k += 4) {
        a0 = fmaf(xs[k + 0], Wp[(k + 0) * D], a0);
        a1 = fmaf(xs[k + 1], Wp[(k + 1) * D], a1);
        a2 = fmaf(xs[k + 2], Wp[(k + 2) * D], a2);
        a3 = fmaf(xs[k + 3], Wp[(k + 3) * D], a3);
    }
    g_enc_part[c][b][t] = (a0 + a1) + (a2 + a3);
}

/* ================= encoder reduce + norms ================= */
__global__ void enc_reduce(const float* __restrict__ bias) {
    __shared__ float red[4];
    int b = blockIdx.x, t = threadIdx.x;
    float s = bias[t];
#pragma unroll
    for (int c = 0; c < ENC_CHUNKS; c++) s += g_enc_part[c][b][t];
    g_batch[b * D + t] = s;
    float sq = s * s;
#pragma unroll
    for (int o = 16; o > 0; o >>= 1) sq += __shfl_down_sync(0xffffffffu, sq, o);
    if ((t & 31) == 0) red[t >> 5] = sq;
    __syncthreads();
    if (t == 0) g_anorm[b] = red[0] + red[1] + red[2] + red[3];
}

/* ---- convert one tile into 2 bf16 row-major swizzled planes + partial norms ----
   thread t: row r = t&127, half h = t>>7 (chunks cc = 8h..8h+7).
   plane phys: r*256 + ((cc ^ (r&7))<<4).  STS.128 conflict-free per quarter-warp. */
__device__ __forceinline__ void convert_tile(const float* __restrict__ reps, int rowbase,
                                             char* smem, int buf, int t, float* npart) {
    int r = t & 127, h = t >> 7;
    const float4* src = (const float4*)(reps + (size_t)(rowbase + r) * D + h * 64);
    char* pbase = smem + ABUF(buf) + r * 256;
    unsigned rsw = (unsigned)(r & 7);
    float nacc = 0.f;
#pragma unroll
    for (int i = 0; i < 8; i++) {
        float4 fa = src[2 * i], fb = src[2 * i + 1];
        const float v[8] = {fa.x, fa.y, fa.z, fa.w, fb.x, fb.y, fb.z, fb.w};
        unsigned w0[4], w1[4];
#pragma unroll
        for (int q = 0; q < 4; q++) {
            float va = v[2 * q], vb = v[2 * q + 1];
            unsigned a0, a1, b0, b1;
            split2(va, a0, a1);
            split2(vb, b0, b1);
            w0[q] = packbf(a0, b0);
            w1[q] = packbf(a1, b1);
            nacc = fmaf(va, va, fmaf(vb, vb, nacc));
        }
        unsigned cc = (unsigned)(8 * h + i);
        char* dst = pbase + ((cc ^ rsw) << 4);
        *(uint4*)dst             = make_uint4(w0[0], w0[1], w0[2], w0[3]);
        *(uint4*)(dst + APLANE)  = make_uint4(w1[0], w1[1], w1[2], w1[3]);
    }
    npart[(buf * 2 + h) * 128 + r] = nacc;
}

/* ================= main distance kernel: 3-term split-bf16 mma.sync ================= */
__global__ void __launch_bounds__(256, 1) dist_kernel(const float* __restrict__ reps) {
    extern __shared__ char smem[];
    float* npart = (float*)(smem + NPART_OFF);
    unsigned sb = smem_u32(smem);

    int t = threadIdx.x, wid = t >> 5, lane = t & 31;
    int g = lane >> 2, qt = lane & 3;
    int bid = blockIdx.x;

    /* ---- build B fragment table (planes 0,1) once — layout identical to R9 (verified) ---- */
    for (int e = t; e < 2048; e += 256) {
        int le = e & 31, nb = (e >> 5) & 3, kk = (e >> 7) & 7, p = e >> 10;
        int ge = le >> 2, te = le & 3;
        int bcol = 8 * nb + ge;
        int k0 = 16 * kk + 2 * te;
        unsigned hh[4][3];
#pragma unroll
        for (int q = 0; q < 4; q++) {
            int k = k0 + (q >> 1) * 8 + (q & 1);
            split3(g_batch[bcol * D + k], hh[q][0], hh[q][1], hh[q][2]);
        }
        uint2 w2;
        w2.x = packbf(hh[0][p], hh[1][p]);
        w2.y = packbf(hh[2][p], hh[3][p]);
        *(uint2*)(smem + BT_OFF + ((size_t)((p * 8 + kk) * 4 + nb)) * 256 + le * 8) = w2;
    }

    convert_tile(reps, bid * TILE_N, smem, 0, t, npart);
    __syncthreads();

    /* per-lane ldmatrix address pieces (row/swizzle fixed per lane) */
    unsigned lrow = (unsigned)(lane & 15);
    unsigned lhi  = (unsigned)(lane >> 4);
    unsigned lsw  = (unsigned)(lane & 7);
    unsigned arow = (unsigned)(wid * 16) * 256u + lrow * 256u;

    /* 8 per-batch top-5 lists: list li = nb*2+s covers batch 8*nb + 2*qt + s */
    float tk[8][5]; int tn[8][5];
#pragma unroll
    for (int li = 0; li < 8; li++)
#pragma unroll
        for (int j = 0; j < 5; j++) { tk[li][j] = 3.0e38f; tn[li][j] = 0; }

    int cur = 0;
    for (int tile = bid; tile < NTILES; tile += GRID_MAIN) {
        int tb = tile * TILE_N;

        float acc[4][4];
#pragma unroll
        for (int nb = 0; nb < 4; nb++)
#pragma unroll
            for (int q = 0; q < 4; q++) acc[nb][q] = 0.f;

        unsigned abase = sb + (unsigned)ABUF(cur) + arow;
        const char* btab = smem + BT_OFF + lane * 8;
#pragma unroll 2
        for (int kk = 0; kk < 8; kk++) {
            unsigned cc = (unsigned)(2 * kk) + lhi;
            unsigned aaddr = abase + ((cc ^ lsw) << 4);
            uint4 A0 = ldsm_x4(aaddr);
            uint4 A1 = ldsm_x4(aaddr + APLANE);
#pragma unroll
            for (int nb = 0; nb < 4; nb++) {
                uint2 B0 = *(const uint2*)(btab + (size_t)((0 * 8 + kk) * 4 + nb) * 256);
                uint2 B1 = *(const uint2*)(btab + (size_t)((1 * 8 + kk) * 4 + nb) * 256);
                mma16816(acc[nb], A0, B0);
                mma16816(acc[nb], A0, B1);
                mma16816(acc[nb], A1, B0);
            }
        }

        /* ---- keys + insert (identical mapping to R9, which passed) ---- */
        float nn0 = npart[(cur * 2 + 0) * 128 + wid * 16 + g] +
                    npart[(cur * 2 + 1) * 128 + wid * 16 + g];
        float nn1 = npart[(cur * 2 + 0) * 128 + wid * 16 + g + 8] +
                    npart[(cur * 2 + 1) * 128 + wid * 16 + g + 8];
        int r0 = tb + wid * 16 + g;
#pragma unroll
        for (int nb = 0; nb < 4; nb++) {
#pragma unroll
            for (int s = 0; s < 2; s++) {
                int li = nb * 2 + s;
                float k0v = nn0 - 2.0f * acc[nb][s];
                float k1v = nn1 - 2.0f * acc[nb][2 + s];
#pragma unroll
                for (int which = 0; which < 2; which++) {
                    float kv = which ? k1v : k0v;
                    int   iv = which ? (r0 + 8) : r0;
                    if (kv < tk[li][4]) {
                        tk[li][4] = kv; tn[li][4] = iv;
#pragma unroll
                        for (int m = 4; m > 0; m--) {
                            if (tk[li][m] < tk[li][m - 1]) {
                                float fk = tk[li][m]; tk[li][m] = tk[li][m - 1]; tk[li][m - 1] = fk;
                                int ii = tn[li][m]; tn[li][m] = tn[li][m - 1]; tn[li][m - 1] = ii;
                            }
                        }
                    }
                }
            }
        }

        int next = tile + GRID_MAIN;
        if (next < NTILES)
            convert_tile(reps, next * TILE_N, smem, cur ^ 1, t, npart);
        __syncthreads();
        cur ^= 1;
    }

    /* ---- merge: dump lists to smem (reuse A buffers), thread b<32 scans ---- */
    float* mk = (float*)smem;              /* [256][8][5] keys */
    int*   mi = (int*)(smem + 49152);      /* [256][8][5] idx  */
#pragma unroll
    for (int li = 0; li < 8; li++)
#pragma unroll
        for (int j = 0; j < 5; j++) {
            mk[(t * 8 + li) * 5 + j] = tk[li][j];
            mi[(t * 8 + li) * 5 + j] = tn[li][j];
        }
    __syncthreads();

    if (t < 32) {
        int b = t;
        int li = (b >> 3) * 2 + (b & 1);
        int qb = (b >> 1) & 3;
        float fk[5]; int fn[5];
#pragma unroll
        for (int j = 0; j < 5; j++) { fk[j] = 3.0e38f; fn[j] = 0; }
        for (int m = 0; m < 64; m++) {
            int tt = qb + 4 * m;
            int base = (tt * 8 + li) * 5;
#pragma unroll
            for (int j = 0; j < 5; j++) {
                float kv = mk[base + j];
                if (kv < fk[4]) {
                    int iv = mi[base + j];
                    fk[4] = kv; fn[4] = iv;
#pragma unroll
                    for (int m2 = 4; m2 > 0; m2--) {
                        if (fk[m2] < fk[m2 - 1]) {
                            float a2 = fk[m2]; fk[m2] = fk[m2 - 1]; fk[m2 - 1] = a2;
                            int i2 = fn[m2]; fn[m2] = fn[m2 - 1]; fn[m2 - 1] = i2;
                        }
                    }
                } else break;  /* lists sorted */
            }
        }
        int basec = (b * GRID_MAIN + bid) * KSEL;
#pragma unroll
        for (int j = 0; j < 5; j++) { g_ckey[basec + j] = fk[j]; g_cidx[basec + j] = fn[j]; }
    }
}

/* ================= final: merge 740 candidates/batch, softmax, gather ================= */
__global__ void __launch_bounds__(256) final_kernel(const float* __restrict__ actions,
                                                    float* __restrict__ out) {
    __shared__ float skey[8 * KSEL];
    __shared__ int   sidx[8 * KSEL];
    int b = blockIdx.x, t = threadIdx.x;
    int w = t >> 5, lane = t & 31;

    float tk[5]; int tn[5];
#pragma unroll
    for (int j = 0; j < 5; j++) { tk[j] = 3.0e38f; tn[j] = 0; }

    const int total = GRID_MAIN * KSEL;
    const float* ck = g_ckey + b * total;
    const int*   ci = g_cidx + b * total;
    for (int i = t; i < total; i += 256) {
        float key = ck[i];
        if (key < tk[4]) {
            int idx = ci[i];
            tk[4] = key; tn[4] = idx;
#pragma unroll
            for (int j = 4; j > 0; j--) {
                if (tk[j] < tk[j - 1]) {
                    float fk = tk[j]; tk[j] = tk[j - 1]; tk[j - 1] = fk;
                    int ii = tn[j]; tn[j] = tn[j - 1]; tn[j - 1] = ii;
                }
            }
        }
    }
#pragma unroll
    for (int o = 16; o > 0; o >>= 1) {
        float ok[5]; int on[5];
#pragma unroll
        for (int j = 0; j < 5; j++) {
            ok[j] = __shfl_xor_sync(0xffffffffu, tk[j], o);
            on[j] = __shfl_xor_sync(0xffffffffu, tn[j], o);
        }
#pragma unroll
        for (int j = 0; j < 5; j++) {
            float key = ok[j]; int idx = on[j];
            if (key < tk[4]) {
                tk[4] = key; tn[4] = idx;
#pragma unroll
                for (int m = 4; m > 0; m--) {
                    if (tk[m] < tk[m - 1]) {
                        float fk = tk[m]; tk[m] = tk[m - 1]; tk[m - 1] = fk;
                        int ii = tn[m]; tn[m] = tn[m - 1]; tn[m - 1] = ii;
                    }
                }
            }
        }
    }
    if (lane == 0) {
#pragma unroll
        for (int j = 0; j < 5; j++) { skey[w * KSEL + j] = tk[j]; sidx[w * KSEL + j] = tn[j]; }
    }
    __syncthreads();

    if (t == 0) {
        float fk[5]; int fn[5];
#pragma unroll
        for (int j = 0; j < 5; j++) { fk[j] = skey[j]; fn[j] = sidx[j]; }
        for (int i = KSEL; i < 8 * KSEL; i++) {
            float key = skey[i];
            if (key < fk[4]) {
                int idx = sidx[i];
                fk[4] = key; fn[4] = idx;
#pragma unroll
                for (int m = 4; m > 0; m--) {
                    if (fk[m] < fk[m - 1]) {
                        float a2 = fk[m]; fk[m] = fk[m - 1]; fk[m - 1] = a2;
                        int i2 = fn[m]; fn[m] = fn[m - 1]; fn[m - 1] = i2;
                    }
                }
            }
        }
        float an = g_anorm[b];
        float dloc[KSEL];
        float dmin = 3.0e38f;
#pragma unroll
        for (int j = 0; j < KSEL; j++) {
            dloc[j] = sqrtf(fmaxf(an + fk[j], 1e-12f));
            dmin = fminf(dmin, dloc[j]);
        }
        float wsum = 0.f;
        float pred[ADIM];
#pragma unroll
        for (int a = 0; a < ADIM; a++) pred[a] = 0.f;
#pragma unroll
        for (int j = 0; j < KSEL; j++) {
            float wgt = expf(-(dloc[j] - dmin));
            wsum += wgt;
            const float* arow = actions + (size_t)fn[j] * ADIM;
#pragma unroll
            for (int a = 0; a < ADIM; a++) pred[a] = fmaf(wgt, arow[a], pred[a]);
        }
        float inv = 1.0f / wsum;
#pragma unroll
        for (int a = 0; a < ADIM; a++) out[b * ADIM + a] = pred[a] * inv;
    }
}

/* ================= launch ================= */
extern "C" void kernel_launch(void* const* d_in, const int* in_sizes, int n_in,
                              void* d_out, int out_size) {
    (void)in_sizes; (void)n_in; (void)out_size;
    const float* x       = (const float*)d_in[0];
    const float* W       = (const float*)d_in[1];
    const float* bias    = (const float*)d_in[2];
    const float* reps    = (const float*)d_in[3];
    const float* actions = (const float*)d_in[4];
    float* out = (float*)d_out;

    cudaFuncSetAttribute(dist_kernel, cudaFuncAttributeMaxDynamicSharedMemorySize, SMEM_TOTAL);

    enc_partial<<<dim3(B, ENC_CHUNKS), 128>>>(x, W);
    enc_reduce<<<B, 128>>>(bias);
    dist_kernel<<<GRID_MAIN, 256, SMEM_TOTAL>>>(reps);
    final_kernel<<<B, 256>>>(actions, out);
}

// round 12
// speedup vs baseline: 1.7133x; 1.0873x over previous
#include <cuda_runtime.h>
#include <math.h>
#include <stdint.h>

#define B 32
#define DIN 2048
#define D 128
#define NREPS 400000
#define ADIM 7
#define KSEL 5
#define KRESC 16                  /* exact-rescore candidate count */

#define GRID_MAIN 296
#define TILE_N 128
#define NTILES (NREPS / TILE_N)   /* 3125, exact */
#define ENC_CHUNKS 16

/* smem layout (bytes) */
#define ABUF(buf)   ((buf) * 32768)   /* 1 bf16 plane: 128 rows x 256B, XOR-swizzled */
#define BT_OFF      65536             /* B frag table: [kk*4+nb][lane*8] = 8192 B */
#define NPART_OFF   73728             /* [buf][128] floats = 1024 B */
#define SMEM_TOTAL  74752

/* ---------------- device scratch ---------------- */
__device__ float g_enc_part[ENC_CHUNKS][B][D];
__device__ float g_batch[B * D];
__device__ float g_anorm[B];
__device__ float g_ckey[B * GRID_MAIN * KSEL];
__device__ int   g_cidx[B * GRID_MAIN * KSEL];

/* ---------------- helpers ---------------- */
__device__ __forceinline__ unsigned cvtbf2(float hi, float lo) {  /* d.hi=cvt(hi), d.lo=cvt(lo) */
    unsigned r;
    asm("cvt.rn.bf16x2.f32 %0, %1, %2;" : "=r"(r) : "f"(hi), "f"(lo));
    return r;
}
__device__ __forceinline__ void mma16816(float* c, uint4 a, uint2 b) {
    asm volatile(
        "mma.sync.aligned.m16n8k16.row.col.f32.bf16.bf16.f32 "
        "{%0,%1,%2,%3}, {%4,%5,%6,%7}, {%8,%9}, {%0,%1,%2,%3};"
        : "+f"(c[0]), "+f"(c[1]), "+f"(c[2]), "+f"(c[3])
        : "r"(a.x), "r"(a.y), "r"(a.z), "r"(a.w), "r"(b.x), "r"(b.y));
}
__device__ __forceinline__ uint4 ldsm_x4(unsigned addr) {
    uint4 r;
    asm volatile("ldmatrix.sync.aligned.m8n8.x4.shared.b16 {%0,%1,%2,%3}, [%4];"
                 : "=r"(r.x), "=r"(r.y), "=r"(r.z), "=r"(r.w) : "r"(addr));
    return r;
}
__device__ __forceinline__ unsigned smem_u32(const void* p) {
    unsigned a;
    asm("{ .reg .u64 t; cvta.to.shared.u64 t, %1; cvt.u32.u64 %0, t; }" : "=r"(a) : "l"(p));
    return a;
}

/* ================= encoder split-K partial ================= */
__global__ void enc_partial(const float* __restrict__ x,
                            const float* __restrict__ W) {
    __shared__ float xs[128];
    int b = blockIdx.x, c = blockIdx.y, t = threadIdx.x;
    xs[t] = x[b * DIN + c * 128 + t];
    __syncthreads();
    const float* Wp = W + (c * 128) * D + t;
    float a0 = 0.f, a1 = 0.f, a2 = 0.f, a3 = 0.f;
#pragma unroll
    for (int k = 0; k < 128; k += 4) {
        a0 = fmaf(xs[k + 0], Wp[(k + 0) * D], a0);
        a1 = fmaf(xs[k + 1], Wp[(k + 1) * D], a1);
        a2 = fmaf(xs[k + 2], Wp[(k + 2) * D], a2);
        a3 = fmaf(xs[k + 3], Wp[(k + 3) * D], a3);
    }
    g_enc_part[c][b][t] = (a0 + a1) + (a2 + a3);
}

/* ================= encoder reduce + norms ================= */
__global__ void enc_reduce(const float* __restrict__ bias) {
    __shared__ float red[4];
    int b = blockIdx.x, t = threadIdx.x;
    float s = bias[t];
#pragma unroll
    for (int c = 0; c < ENC_CHUNKS; c++) s += g_enc_part[c][b][t];
    g_batch[b * D + t] = s;
    float sq = s * s;
#pragma unroll
    for (int o = 16; o > 0; o >>= 1) sq += __shfl_down_sync(0xffffffffu, sq, o);
    if ((t & 31) == 0) red[t >> 5] = sq;
    __syncthreads();
    if (t == 0) g_anorm[b] = red[0] + red[1] + red[2] + red[3];
}

/* ---- convert one tile: warp wid handles rows wid*16..+15; one coalesced
   LDG.128 per row (lane l = dims 4l..4l+3), cvt.rn to bf16, STS.64 into
   swizzled plane (conflict-free), exact fp32 row norm via shuffle.        */
__device__ __forceinline__ void convert_tile(const float* __restrict__ reps, int rowbase,
                                             char* smem, int buf, int wid, int lane,
                                             float* npart) {
#pragma unroll
    for (int i = 0; i < 16; i++) {
        int r = wid * 16 + i;
        float4 v = ((const float4*)(reps + (size_t)(rowbase + r) * D))[lane];
        unsigned w0 = cvtbf2(v.y, v.x);
        unsigned w1 = cvtbf2(v.w, v.z);
        float na = fmaf(v.x, v.x, fmaf(v.y, v.y, fmaf(v.z, v.z, v.w * v.w)));
#pragma unroll
        for (int o = 16; o > 0; o >>= 1) na += __shfl_xor_sync(0xffffffffu, na, o);
        if (lane == 0) npart[buf * 128 + r] = na;
        unsigned off = (unsigned)ABUF(buf) + (unsigned)r * 256u
                     + ((((unsigned)(lane >> 1)) ^ ((unsigned)(r & 7))) << 4)
                     + ((unsigned)(lane & 1)) * 8u;
        *(uint2*)(smem + off) = make_uint2(w0, w1);
    }
}

/* ================= main distance kernel: 1-term bf16 mma.sync ================= */
__global__ void __launch_bounds__(256, 2) dist_kernel(const float* __restrict__ reps) {
    extern __shared__ char smem[];
    float* npart = (float*)(smem + NPART_OFF);
    unsigned sb = smem_u32(smem);

    int t = threadIdx.x, wid = t >> 5, lane = t & 31;
    int g = lane >> 2;
    int bid = blockIdx.x;

    /* ---- B fragment table (single rounded plane); layout as R9/R11 (verified) ---- */
    for (int e = t; e < 1024; e += 256) {
        int le = e & 31, nb = (e >> 5) & 3, kk = e >> 7;
        int ge = le >> 2, te = le & 3;
        int bcol = 8 * nb + ge;
        int k0 = 16 * kk + 2 * te;
        float v0 = g_batch[bcol * D + k0];
        float v1 = g_batch[bcol * D + k0 + 1];
        float v2 = g_batch[bcol * D + k0 + 8];
        float v3 = g_batch[bcol * D + k0 + 9];
        uint2 w2;
        w2.x = cvtbf2(v1, v0);
        w2.y = cvtbf2(v3, v2);
        *(uint2*)(smem + BT_OFF + (size_t)(kk * 4 + nb) * 256 + le * 8) = w2;
    }

    convert_tile(reps, bid * TILE_N, smem, 0, wid, lane, npart);
    __syncthreads();

    unsigned lrow = (unsigned)(lane & 15);
    unsigned lhi  = (unsigned)(lane >> 4);
    unsigned lsw  = (unsigned)(lane & 7);
    unsigned arow = ((unsigned)(wid * 16) + lrow) * 256u;

    /* per-thread top-4 lists: list li = nb*2+s covers batch 8*nb + 2*(lane&3) + s */
    float tk[8][4]; int tn[8][4];
#pragma unroll
    for (int li = 0; li < 8; li++)
#pragma unroll
        for (int j = 0; j < 4; j++) { tk[li][j] = 3.0e38f; tn[li][j] = 0; }

    int cur = 0;
    for (int tile = bid; tile < NTILES; tile += GRID_MAIN) {
        int tb = tile * TILE_N;

        float acc[4][4];
#pragma unroll
        for (int nb = 0; nb < 4; nb++)
#pragma unroll
            for (int q = 0; q < 4; q++) acc[nb][q] = 0.f;

        unsigned abase = sb + (unsigned)ABUF(cur) + arow;
        const char* btab = smem + BT_OFF + lane * 8;
#pragma unroll
        for (int kk = 0; kk < 8; kk++) {
            unsigned cc = (unsigned)(2 * kk) + lhi;
            uint4 A0 = ldsm_x4(abase + ((cc ^ lsw) << 4));
#pragma unroll
            for (int nb = 0; nb < 4; nb++) {
                uint2 B0 = *(const uint2*)(btab + (size_t)(kk * 4 + nb) * 256);
                mma16816(acc[nb], A0, B0);
            }
        }

        /* keys + insert (mapping verified in R9/R11) */
        float nn0 = npart[cur * 128 + wid * 16 + g];
        float nn1 = npart[cur * 128 + wid * 16 + g + 8];
        int r0 = tb + wid * 16 + g;
#pragma unroll
        for (int nb = 0; nb < 4; nb++) {
#pragma unroll
            for (int s = 0; s < 2; s++) {
                int li = nb * 2 + s;
                float k0v = nn0 - 2.0f * acc[nb][s];
                float k1v = nn1 - 2.0f * acc[nb][2 + s];
#pragma unroll
                for (int which = 0; which < 2; which++) {
                    float kv = which ? k1v : k0v;
                    int   iv = which ? (r0 + 8) : r0;
                    if (kv < tk[li][3]) {
                        tk[li][3] = kv; tn[li][3] = iv;
#pragma unroll
                        for (int m = 3; m > 0; m--) {
                            if (tk[li][m] < tk[li][m - 1]) {
                                float fk = tk[li][m]; tk[li][m] = tk[li][m - 1]; tk[li][m - 1] = fk;
                                int ii = tn[li][m]; tn[li][m] = tn[li][m - 1]; tn[li][m - 1] = ii;
                            }
                        }
                    }
                }
            }
        }

        int next = tile + GRID_MAIN;
        if (next < NTILES)
            convert_tile(reps, next * TILE_N, smem, cur ^ 1, wid, lane, npart);
        __syncthreads();
        cur ^= 1;
    }

    /* ---- merge: dump [8][4] lists to smem (reuse plane bufs), thread b<32 scans ---- */
    float* mk = (float*)smem;              /* [256][8][4] keys = 32KB */
    int*   mi = (int*)(smem + 32768);      /* [256][8][4] idx  = 32KB */
#pragma unroll
    for (int li = 0; li < 8; li++)
#pragma unroll
        for (int j = 0; j < 4; j++) {
            mk[(t * 8 + li) * 4 + j] = tk[li][j];
            mi[(t * 8 + li) * 4 + j] = tn[li][j];
        }
    __syncthreads();

    if (t < 32) {
        int b = t;
        int li = (b >> 3) * 2 + (b & 1);
        int qb = (b >> 1) & 3;
        float fk[5]; int fn[5];
#pragma unroll
        for (int j = 0; j < 5; j++) { fk[j] = 3.0e38f; fn[j] = 0; }
        for (int m = 0; m < 64; m++) {
            int tt = qb + 4 * m;
            int base = (tt * 8 + li) * 4;
#pragma unroll
            for (int j = 0; j < 4; j++) {
                float kv = mk[base + j];
                if (kv < fk[4]) {
                    int iv = mi[base + j];
                    fk[4] = kv; fn[4] = iv;
#pragma unroll
                    for (int m2 = 4; m2 > 0; m2--) {
                        if (fk[m2] < fk[m2 - 1]) {
                            float a2 = fk[m2]; fk[m2] = fk[m2 - 1]; fk[m2 - 1] = a2;
                            int i2 = fn[m2]; fn[m2] = fn[m2 - 1]; fn[m2 - 1] = i2;
                        }
                    }
                } else break;   /* lists sorted */
            }
        }
        int basec = (b * GRID_MAIN + bid) * KSEL;
#pragma unroll
        for (int j = 0; j < 5; j++) { g_ckey[basec + j] = fk[j]; g_cidx[basec + j] = fn[j]; }
    }
}

/* ================= final: approx top-16, exact fp32 rescore, softmax ================= */
__global__ void __launch_bounds__(256) final_kernel(const float* __restrict__ actions,
                                                    const float* __restrict__ reps,
                                                    float* __restrict__ out) {
    __shared__ float mk[1280];
    __shared__ int   mi[1280];
    __shared__ float t16k[KRESC];
    __shared__ int   t16i[KRESC];
    __shared__ float exk[KRESC];
    int b = blockIdx.x, t = threadIdx.x;
    int w = t >> 5, lane = t & 31;

    const int total = GRID_MAIN * KSEL;   /* 1480, contiguous per batch */
    const float* ck = g_ckey + b * total;
    const int*   ci = g_cidx + b * total;

    /* phase 1: per-thread top-5 of <=6 strided entries -> smem dump */
    {
        float tk[5]; int tn[5];
#pragma unroll
        for (int j = 0; j < 5; j++) { tk[j] = 3.0e38f; tn[j] = 0; }
        for (int i = t; i < total; i += 256) {
            float key = ck[i];
            if (key < tk[4]) {
                int idx = ci[i];
                tk[4] = key; tn[4] = idx;
#pragma unroll
                for (int j = 4; j > 0; j--) {
                    if (tk[j] < tk[j - 1]) {
                        float fk = tk[j]; tk[j] = tk[j - 1]; tk[j - 1] = fk;
                        int ii = tn[j]; tn[j] = tn[j - 1]; tn[j - 1] = ii;
                    }
                }
            }
        }
#pragma unroll
        for (int j = 0; j < 5; j++) { mk[t * 5 + j] = tk[j]; mi[t * 5 + j] = tn[j]; }
    }
    __syncthreads();

    /* phase 2: warp 0 builds global approx top-16 from the 1280 smem entries */
    if (w == 0) {
        float fk[KRESC]; int fn[KRESC];
#pragma unroll
        for (int j = 0; j < KRESC; j++) { fk[j] = 3.0e38f; fn[j] = 0; }
        for (int e = lane; e < 1280; e += 32) {
            float kv = mk[e];
            if (kv < fk[KRESC - 1]) {
                int iv = mi[e];
                fk[KRESC - 1] = kv; fn[KRESC - 1] = iv;
#pragma unroll
                for (int m = KRESC - 1; m > 0; m--) {
                    if (fk[m] < fk[m - 1]) {
                        float a2 = fk[m]; fk[m] = fk[m - 1]; fk[m - 1] = a2;
                        int i2 = fn[m]; fn[m] = fn[m - 1]; fn[m - 1] = i2;
                    }
                }
            }
        }
#pragma unroll
        for (int o = 16; o > 0; o >>= 1) {
            float ok[KRESC]; int on[KRESC];
#pragma unroll
            for (int j = 0; j < KRESC; j++) {
                ok[j] = __shfl_xor_sync(0xffffffffu, fk[j], o);
                on[j] = __shfl_xor_sync(0xffffffffu, fn[j], o);
            }
#pragma unroll
            for (int j = 0; j < KRESC; j++) {
                float kv = ok[j]; int iv = on[j];
                if (kv < fk[KRESC - 1]) {
                    fk[KRESC - 1] = kv; fn[KRESC - 1] = iv;
#pragma unroll
                    for (int m = KRESC - 1; m > 0; m--) {
                        if (fk[m] < fk[m - 1]) {
                            float a2 = fk[m]; fk[m] = fk[m - 1]; fk[m - 1] = a2;
                            int i2 = fn[m]; fn[m] = fn[m - 1]; fn[m - 1] = i2;
                        }
                    }
                }
            }
        }
        if (lane == 0) {
#pragma unroll
            for (int j = 0; j < KRESC; j++) { t16k[j] = fk[j]; t16i[j] = fn[j]; }
        }
    }
    __syncthreads();

    /* phase 3: exact fp32 rescore — warp w handles candidates 2w, 2w+1 */
    {
        const float4* av4 = (const float4*)(g_batch + b * D);
        float4 av = av4[lane];
#pragma unroll
        for (int cc = 0; cc < 2; cc++) {
            int c = 2 * w + cc;
            int idx = t16i[c];
            float4 rv = ((const float4*)(reps + (size_t)idx * D))[lane];
            float dot = fmaf(av.x, rv.x, fmaf(av.y, rv.y, fmaf(av.z, rv.z, av.w * rv.w)));
            float rn  = fmaf(rv.x, rv.x, fmaf(rv.y, rv.y, fmaf(rv.z, rv.z, rv.w * rv.w)));
#pragma unroll
            for (int o = 16; o > 0; o >>= 1) {
                dot += __shfl_xor_sync(0xffffffffu, dot, o);
                rn  += __shfl_xor_sync(0xffffffffu, rn, o);
            }
            if (lane == 0) exk[c] = rn - 2.0f * dot;
        }
    }
    __syncthreads();

    /* phase 4: exact top-5 of 16, softmax, gather actions */
    if (t == 0) {
        float fk[5]; int fn[5];
#pragma unroll
        for (int j = 0; j < 5; j++) { fk[j] = 3.0e38f; fn[j] = 0; }
#pragma unroll
        for (int c = 0; c < KRESC; c++) {
            float kv = exk[c];
            if (kv < fk[4]) {
                int iv = t16i[c];
                fk[4] = kv; fn[4] = iv;
#pragma unroll
                for (int m = 4; m > 0; m--) {
                    if (fk[m] < fk[m - 1]) {
                        float a2 = fk[m]; fk[m] = fk[m - 1]; fk[m - 1] = a2;
                        int i2 = fn[m]; fn[m] = fn[m - 1]; fn[m - 1] = i2;
                    }
                }
            }
        }
        float an = g_anorm[b];
        float dloc[KSEL];
        float dmin = 3.0e38f;
#pragma unroll
        for (int j = 0; j < KSEL; j++) {
            dloc[j] = sqrtf(fmaxf(an + fk[j], 1e-12f));
            dmin = fminf(dmin, dloc[j]);
        }
        float wsum = 0.f;
        float pred[ADIM];
#pragma unroll
        for (int a = 0; a < ADIM; a++) pred[a] = 0.f;
#pragma unroll
        for (int j = 0; j < KSEL; j++) {
            float wgt = expf(-(dloc[j] - dmin));
            wsum += wgt;
            const float* arow = actions + (size_t)fn[j] * ADIM;
#pragma unroll
            for (int a = 0; a < ADIM; a++) pred[a] = fmaf(wgt, arow[a], pred[a]);
        }
        float inv = 1.0f / wsum;
#pragma unroll
        for (int a = 0; a < ADIM; a++) out[b * ADIM + a] = pred[a] * inv;
    }
}

/* ================= launch ================= */
extern "C" void kernel_launch(void* const* d_in, const int* in_sizes, int n_in,
                              void* d_out, int out_size) {
    (void)in_sizes; (void)n_in; (void)out_size;
    const float* x       = (const float*)d_in[0];
    const float* W       = (const float*)d_in[1];
    const float* bias    = (const float*)d_in[2];
    const float* reps    = (const float*)d_in[3];
    const float* actions = (const float*)d_in[4];
    float* out = (float*)d_out;

    cudaFuncSetAttribute(dist_kernel, cudaFuncAttributeMaxDynamicSharedMemorySize, SMEM_TOTAL);

    enc_partial<<<dim3(B, ENC_CHUNKS), 128>>>(x, W);
    enc_reduce<<<B, 128>>>(bias);
    dist_kernel<<<GRID_MAIN, 256, SMEM_TOTAL>>>(reps);
    final_kernel<<<B, 256>>>(actions, reps, out);
}

// round 14
// speedup vs baseline: 2.4769x; 1.4457x over previous
#include <cuda_runtime.h>
#include <math.h>
#include <stdint.h>

#define B 32
#define DIN 2048
#define D 128
#define NREPS 400000
#define ADIM 7
#define KSEL 5
#define NCAND 40                  /* 8 warps x depth-5 lists -> exact rescore */

#define GRID_MAIN 296
#define TILE_N 128
#define NTILES (NREPS / TILE_N)   /* 3125, exact */
#define ENC_CHUNKS 16

/* smem layout (bytes) */
#define ABUF(buf)   ((buf) * 32768)   /* 1 bf16 plane: 128 rows x 256B, XOR-swizzled */
#define BT_OFF      65536             /* B frag table: [kk*4+nb][lane*8] = 8192 B */
#define NPART_OFF   73728             /* [buf][128] floats = 1024 B */
#define SMEM_TOTAL  74752

/* ---------------- device scratch ---------------- */
__device__ float g_enc_part[ENC_CHUNKS][B][D];
__device__ float g_batch[B * D];
__device__ float g_anorm[B];
__device__ float g_ckey[B * GRID_MAIN * KSEL];
__device__ int   g_cidx[B * GRID_MAIN * KSEL];

/* ---------------- helpers ---------------- */
__device__ __forceinline__ unsigned cvtbf2(float hi, float lo) {
    unsigned r;
    asm("cvt.rn.bf16x2.f32 %0, %1, %2;" : "=r"(r) : "f"(hi), "f"(lo));
    return r;
}
__device__ __forceinline__ void mma16816(float* c, uint4 a, uint2 b) {
    asm volatile(
        "mma.sync.aligned.m16n8k16.row.col.f32.bf16.bf16.f32 "
        "{%0,%1,%2,%3}, {%4,%5,%6,%7}, {%8,%9}, {%0,%1,%2,%3};"
        : "+f"(c[0]), "+f"(c[1]), "+f"(c[2]), "+f"(c[3])
        : "r"(a.x), "r"(a.y), "r"(a.z), "r"(a.w), "r"(b.x), "r"(b.y));
}
__device__ __forceinline__ uint4 ldsm_x4(unsigned addr) {
    uint4 r;
    asm volatile("ldmatrix.sync.aligned.m8n8.x4.shared.b16 {%0,%1,%2,%3}, [%4];"
                 : "=r"(r.x), "=r"(r.y), "=r"(r.z), "=r"(r.w) : "r"(addr));
    return r;
}
__device__ __forceinline__ unsigned smem_u32(const void* p) {
    unsigned a;
    asm("{ .reg .u64 t; cvta.to.shared.u64 t, %1; cvt.u32.u64 %0, t; }" : "=r"(a) : "l"(p));
    return a;
}

/* ================= encoder split-K partial ================= */
__global__ void enc_partial(const float* __restrict__ x,
                            const float* __restrict__ W) {
    __shared__ float xs[128];
    int b = blockIdx.x, c = blockIdx.y, t = threadIdx.x;
    xs[t] = x[b * DIN + c * 128 + t];
    __syncthreads();
    const float* Wp = W + (c * 128) * D + t;
    float a0 = 0.f, a1 = 0.f, a2 = 0.f, a3 = 0.f;
#pragma unroll
    for (int k = 0; k < 128; k += 4) {
        a0 = fmaf(xs[k + 0], Wp[(k + 0) * D], a0);
        a1 = fmaf(xs[k + 1], Wp[(k + 1) * D], a1);
        a2 = fmaf(xs[k + 2], Wp[(k + 2) * D], a2);
        a3 = fmaf(xs[k + 3], Wp[(k + 3) * D], a3);
    }
    g_enc_part[c][b][t] = (a0 + a1) + (a2 + a3);
}

/* ================= encoder reduce + norms ================= */
__global__ void enc_reduce(const float* __restrict__ bias) {
    __shared__ float red[4];
    int b = blockIdx.x, t = threadIdx.x;
    float s = bias[t];
#pragma unroll
    for (int c = 0; c < ENC_CHUNKS; c++) s += g_enc_part[c][b][t];
    g_batch[b * D + t] = s;
    float sq = s * s;
#pragma unroll
    for (int o = 16; o > 0; o >>= 1) sq += __shfl_down_sync(0xffffffffu, sq, o);
    if ((t & 31) == 0) red[t >> 5] = sq;
    __syncthreads();
    if (t == 0) g_anorm[b] = red[0] + red[1] + red[2] + red[3];
}

/* ---- convert one tile: warp wid handles rows wid*16..+15 (verified R12) ---- */
__device__ __forceinline__ void convert_tile(const float* __restrict__ reps, int rowbase,
                                             char* smem, int buf, int wid, int lane,
                                             float* npart) {
#pragma unroll
    for (int i = 0; i < 16; i++) {
        int r = wid * 16 + i;
        float4 v = ((const float4*)(reps + (size_t)(rowbase + r) * D))[lane];
        unsigned w0 = cvtbf2(v.y, v.x);
        unsigned w1 = cvtbf2(v.w, v.z);
        float na = fmaf(v.x, v.x, fmaf(v.y, v.y, fmaf(v.z, v.z, v.w * v.w)));
#pragma unroll
        for (int o = 16; o > 0; o >>= 1) na += __shfl_xor_sync(0xffffffffu, na, o);
        if (lane == 0) npart[buf * 128 + r] = na;
        unsigned off = (unsigned)ABUF(buf) + (unsigned)r * 256u
                     + ((((unsigned)(lane >> 1)) ^ ((unsigned)(r & 7))) << 4)
                     + ((unsigned)(lane & 1)) * 8u;
        *(uint2*)(smem + off) = make_uint2(w0, w1);
    }
}

/* ================= main distance kernel: 1-term bf16 mma.sync (verified R12) ================= */
__global__ void __launch_bounds__(256, 2) dist_kernel(const float* __restrict__ reps) {
    extern __shared__ char smem[];
    float* npart = (float*)(smem + NPART_OFF);
    unsigned sb = smem_u32(smem);

    int t = threadIdx.x, wid = t >> 5, lane = t & 31;
    int g = lane >> 2;
    int bid = blockIdx.x;

    for (int e = t; e < 1024; e += 256) {
        int le = e & 31, nb = (e >> 5) & 3, kk = e >> 7;
        int ge = le >> 2, te = le & 3;
        int bcol = 8 * nb + ge;
        int k0 = 16 * kk + 2 * te;
        float v0 = g_batch[bcol * D + k0];
        float v1 = g_batch[bcol * D + k0 + 1];
        float v2 = g_batch[bcol * D + k0 + 8];
        float v3 = g_batch[bcol * D + k0 + 9];
        uint2 w2;
        w2.x = cvtbf2(v1, v0);
        w2.y = cvtbf2(v3, v2);
        *(uint2*)(smem + BT_OFF + (size_t)(kk * 4 + nb) * 256 + le * 8) = w2;
    }

    convert_tile(reps, bid * TILE_N, smem, 0, wid, lane, npart);
    __syncthreads();

    unsigned lrow = (unsigned)(lane & 15);
    unsigned lhi  = (unsigned)(lane >> 4);
    unsigned lsw  = (unsigned)(lane & 7);
    unsigned arow = ((unsigned)(wid * 16) + lrow) * 256u;

    float tk[8][4]; int tn[8][4];
#pragma unroll
    for (int li = 0; li < 8; li++)
#pragma unroll
        for (int j = 0; j < 4; j++) { tk[li][j] = 3.0e38f; tn[li][j] = 0; }

    int cur = 0;
    for (int tile = bid; tile < NTILES; tile += GRID_MAIN) {
        int tb = tile * TILE_N;

        float acc[4][4];
#pragma unroll
        for (int nb = 0; nb < 4; nb++)
#pragma unroll
            for (int q = 0; q < 4; q++) acc[nb][q] = 0.f;

        unsigned abase = sb + (unsigned)ABUF(cur) + arow;
        const char* btab = smem + BT_OFF + lane * 8;
#pragma unroll
        for (int kk = 0; kk < 8; kk++) {
            unsigned cc = (unsigned)(2 * kk) + lhi;
            uint4 A0 = ldsm_x4(abase + ((cc ^ lsw) << 4));
#pragma unroll
            for (int nb = 0; nb < 4; nb++) {
                uint2 B0 = *(const uint2*)(btab + (size_t)(kk * 4 + nb) * 256);
                mma16816(acc[nb], A0, B0);
            }
        }

        float nn0 = npart[cur * 128 + wid * 16 + g];
        float nn1 = npart[cur * 128 + wid * 16 + g + 8];
        int r0 = tb + wid * 16 + g;
#pragma unroll
        for (int nb = 0; nb < 4; nb++) {
#pragma unroll
            for (int s = 0; s < 2; s++) {
                int li = nb * 2 + s;
                float k0v = nn0 - 2.0f * acc[nb][s];
                float k1v = nn1 - 2.0f * acc[nb][2 + s];
#pragma unroll
                for (int which = 0; which < 2; which++) {
                    float kv = which ? k1v : k0v;
                    int   iv = which ? (r0 + 8) : r0;
                    if (kv < tk[li][3]) {
                        tk[li][3] = kv; tn[li][3] = iv;
#pragma unroll
                        for (int m = 3; m > 0; m--) {
                            if (tk[li][m] < tk[li][m - 1]) {
                                float fk = tk[li][m]; tk[li][m] = tk[li][m - 1]; tk[li][m - 1] = fk;
                                int ii = tn[li][m]; tn[li][m] = tn[li][m - 1]; tn[li][m - 1] = ii;
                            }
                        }
                    }
                }
            }
        }

        int next = tile + GRID_MAIN;
        if (next < NTILES)
            convert_tile(reps, next * TILE_N, smem, cur ^ 1, wid, lane, npart);
        __syncthreads();
        cur ^= 1;
    }

    float* mk = (float*)smem;
    int*   mi = (int*)(smem + 32768);
#pragma unroll
    for (int li = 0; li < 8; li++)
#pragma unroll
        for (int j = 0; j < 4; j++) {
            mk[(t * 8 + li) * 4 + j] = tk[li][j];
            mi[(t * 8 + li) * 4 + j] = tn[li][j];
        }
    __syncthreads();

    if (t < 32) {
        int b = t;
        int li = (b >> 3) * 2 + (b & 1);
        int qb = (b >> 1) & 3;
        float fk[5]; int fn[5];
#pragma unroll
        for (int j = 0; j < 5; j++) { fk[j] = 3.0e38f; fn[j] = 0; }
        for (int m = 0; m < 64; m++) {
            int tt = qb + 4 * m;
            int base = (tt * 8 + li) * 4;
#pragma unroll
            for (int j = 0; j < 4; j++) {
                float kv = mk[base + j];
                if (kv < fk[4]) {
                    int iv = mi[base + j];
                    fk[4] = kv; fn[4] = iv;
#pragma unroll
                    for (int m2 = 4; m2 > 0; m2--) {
                        if (fk[m2] < fk[m2 - 1]) {
                            float a2 = fk[m2]; fk[m2] = fk[m2 - 1]; fk[m2 - 1] = a2;
                            int i2 = fn[m2]; fn[m2] = fn[m2 - 1]; fn[m2 - 1] = i2;
                        }
                    }
                } else break;
            }
        }
        int basec = (b * GRID_MAIN + bid) * KSEL;
#pragma unroll
        for (int j = 0; j < 5; j++) { g_ckey[basec + j] = fk[j]; g_cidx[basec + j] = fn[j]; }
    }
}

/* ================= final: depth-5 merge -> 40 cands -> exact rescore -> softmax ================= */
__global__ void __launch_bounds__(256) final_kernel(const float* __restrict__ actions,
                                                    const float* __restrict__ reps,
                                                    float* __restrict__ out) {
    __shared__ float wk[NCAND];
    __shared__ int   wi[NCAND];
    __shared__ float exk[NCAND];
    int b = blockIdx.x, t = threadIdx.x;
    int w = t >> 5, lane = t & 31;

    const int total = GRID_MAIN * KSEL;   /* 1480, contiguous per batch */
    const float* ck = g_ckey + b * total;
    const int*   ci = g_cidx + b * total;

    /* phase 1: per-thread top-5 over ~6 coalesced strided entries */
    float tk[5]; int tn[5];
#pragma unroll
    for (int j = 0; j < 5; j++) { tk[j] = 3.0e38f; tn[j] = 0; }
    for (int i = t; i < total; i += 256) {
        float key = ck[i];
        if (key < tk[4]) {
            int idx = ci[i];
            tk[4] = key; tn[4] = idx;
#pragma unroll
            for (int j = 4; j > 0; j--) {
                if (tk[j] < tk[j - 1]) {
                    float fk = tk[j]; tk[j] = tk[j - 1]; tk[j - 1] = fk;
                    int ii = tn[j]; tn[j] = tn[j - 1]; tn[j - 1] = ii;
                }
            }
        }
    }

    /* phase 2: depth-5 warp shuffle merge (R5-verified structure) */
#pragma unroll
    for (int o = 16; o > 0; o >>= 1) {
        float ok[5]; int on[5];
#pragma unroll
        for (int j = 0; j < 5; j++) {
            ok[j] = __shfl_xor_sync(0xffffffffu, tk[j], o);
            on[j] = __shfl_xor_sync(0xffffffffu, tn[j], o);
        }
#pragma unroll
        for (int j = 0; j < 5; j++) {
            float key = ok[j]; int idx = on[j];
            if (key < tk[4]) {
                tk[4] = key; tn[4] = idx;
#pragma unroll
                for (int m = 4; m > 0; m--) {
                    if (tk[m] < tk[m - 1]) {
                        float fk = tk[m]; tk[m] = tk[m - 1]; tk[m - 1] = fk;
                        int ii = tn[m]; tn[m] = tn[m - 1]; tn[m - 1] = ii;
                    }
                }
            }
        }
    }
    if (lane == 0) {
#pragma unroll
        for (int j = 0; j < 5; j++) { wk[w * KSEL + j] = tk[j]; wi[w * KSEL + j] = tn[j]; }
    }
    __syncthreads();

    /* phase 3: exact fp32 rescore of all 40 candidates; warp w does c = w*5..w*5+4 */
    {
        float4 av = ((const float4*)(g_batch + b * D))[lane];
#pragma unroll
        for (int cc = 0; cc < 5; cc++) {
            int c = w * 5 + cc;
            int idx = wi[c];
            float4 rv = ((const float4*)(reps + (size_t)idx * D))[lane];
            float dot = fmaf(av.x, rv.x, fmaf(av.y, rv.y, fmaf(av.z, rv.z, av.w * rv.w)));
            float rn  = fmaf(rv.x, rv.x, fmaf(rv.y, rv.y, fmaf(rv.z, rv.z, rv.w * rv.w)));
#pragma unroll
            for (int o = 16; o > 0; o >>= 1) {
                dot += __shfl_xor_sync(0xffffffffu, dot, o);
                rn  += __shfl_xor_sync(0xffffffffu, rn, o);
            }
            if (lane == 0) exk[c] = rn - 2.0f * dot;
        }
    }
    __syncthreads();

    /* phase 4: exact top-5 of 40, softmax, gather actions */
    if (t == 0) {
        float fk[5]; int fn[5];
#pragma unroll
        for (int j = 0; j < 5; j++) { fk[j] = 3.0e38f; fn[j] = 0; }
#pragma unroll
        for (int c = 0; c < NCAND; c++) {
            float kv = exk[c];
            if (kv < fk[4]) {
                int iv = wi[c];
                fk[4] = kv; fn[4] = iv;
#pragma unroll
                for (int m = 4; m > 0; m--) {
                    if (fk[m] < fk[m - 1]) {
                        float a2 = fk[m]; fk[m] = fk[m - 1]; fk[m - 1] = a2;
                        int i2 = fn[m]; fn[m] = fn[m - 1]; fn[m - 1] = i2;
                    }
                }
            }
        }
        float an = g_anorm[b];
        float dloc[KSEL];
        float dmin = 3.0e38f;
#pragma unroll
        for (int j = 0; j < KSEL; j++) {
            dloc[j] = sqrtf(fmaxf(an + fk[j], 1e-12f));
            dmin = fminf(dmin, dloc[j]);
        }
        float wsum = 0.f;
        float pred[ADIM];
#pragma unroll
        for (int a = 0; a < ADIM; a++) pred[a] = 0.f;
#pragma unroll
        for (int j = 0; j < KSEL; j++) {
            float wgt = expf(-(dloc[j] - dmin));
            wsum += wgt;
            const float* arow = actions + (size_t)fn[j] * ADIM;
#pragma unroll
            for (int a = 0; a < ADIM; a++) pred[a] = fmaf(wgt, arow[a], pred[a]);
        }
        float inv = 1.0f / wsum;
#pragma unroll
        for (int a = 0; a < ADIM; a++) out[b * ADIM + a] = pred[a] * inv;
    }
}

/* ================= launch ================= */
extern "C" void kernel_launch(void* const* d_in, const int* in_sizes, int n_in,
                              void* d_out, int out_size) {
    (void)in_sizes; (void)n_in; (void)out_size;
    const float* x       = (const float*)d_in[0];
    const float* W       = (const float*)d_in[1];
    const float* bias    = (const float*)d_in[2];
    const float* reps    = (const float*)d_in[3];
    const float* actions = (const float*)d_in[4];
    float* out = (float*)d_out;

    cudaFuncSetAttribute(dist_kernel, cudaFuncAttributeMaxDynamicSharedMemorySize, SMEM_TOTAL);

    enc_partial<<<dim3(B, ENC_CHUNKS), 128>>>(x, W);
    enc_reduce<<<B, 128>>>(bias);
    dist_kernel<<<GRID_MAIN, 256, SMEM_TOTAL>>>(reps);
    final_kernel<<<B, 256>>>(actions, reps, out);
}